// round 3
// baseline (speedup 1.0000x reference)
#include <cuda_runtime.h>
#include <math.h>

// Problem constants (shapes are fixed by the reference: D=H=256, E=8, L=64)
#define NT   256     // threads per block
#define BM   64      // rows per block
#define LDT  68      // padded row stride (floats) for transposed smem tiles

// shared memory layout (float offsets)
#define OFF_A1 0                         // [256][LDT]  gate/score tile transposed, also a_T
#define OFF_A2 (256 * LDT)               // [256][LDT]  gl_T / h1_T
#define OFF_B  (2 * 256 * LDT)           // 2 x [64][LDT] weight staging (double buffer)
#define OFF_Z  (OFF_B + 2 * 64 * LDT)    // [64][8] logits scratch
#define OFF_P  (OFF_Z + 512)             // [64][8] probs
#define OFF_EO (OFF_P + 512)             // [64]    weighted expert-output accumulator
#define SMEM_FLOATS (OFF_EO + 64)
#define SMEM_BYTES  (SMEM_FLOATS * 4)

// Load a [64 x 256] fp32 row-major tile from global, store transposed into dst[k][m].
__device__ __forceinline__ void load_tile_T(float* dst, const float* __restrict__ src,
                                            int row0, int N, int t) {
#pragma unroll
    for (int r = 0; r < 16; r++) {
        int p   = t + NT * r;          // 0..1023 float4 slots
        int m   = p >> 6;              // 0..63 row within tile
        int k4  = (p & 63) << 2;       // 0..252 col (float4 aligned)
        int row = row0 + m;
        float4 v = make_float4(0.f, 0.f, 0.f, 0.f);
        if (row < N) v = *(const float4*)(src + (size_t)row * 256 + k4);
        dst[(k4 + 0) * LDT + m] = v.x;
        dst[(k4 + 1) * LDT + m] = v.y;
        dst[(k4 + 2) * LDT + m] = v.z;
        dst[(k4 + 3) * LDT + m] = v.w;
    }
}

// C[64,64] (4x4 per thread) = A_T(256xBM, transposed in smem) @ W[256, ldW] cols [nbase, nbase+64)
// Weight chunks double-buffered through registers to overlap L2 latency with FMA.
__device__ __forceinline__ void gemm64(const float* __restrict__ A_T,
                                       const float* __restrict__ W, int ldW, int nbase,
                                       float* Bst, float c[4][4],
                                       int m0, int n0, int t) {
    float4 st[4];
    int kk_s[4], nn_s[4];
#pragma unroll
    for (int r = 0; r < 4; r++) {
        int i   = t + NT * r;      // 0..1023 float4 slots of a [64k x 64n] chunk
        kk_s[r] = i >> 4;          // 0..63
        nn_s[r] = (i & 15) << 2;   // 0..60
    }
    // prologue: stage chunk 0
#pragma unroll
    for (int r = 0; r < 4; r++)
        st[r] = *(const float4*)(W + kk_s[r] * ldW + nbase + nn_s[r]);
#pragma unroll
    for (int r = 0; r < 4; r++)
        *(float4*)(Bst + kk_s[r] * LDT + nn_s[r]) = st[r];
    __syncthreads();

    for (int kb = 0; kb < 4; kb++) {
        const float* buf = Bst + (kb & 1) * (64 * LDT);
        if (kb < 3) {  // prefetch next chunk into registers (overlaps with FMAs below)
#pragma unroll
            for (int r = 0; r < 4; r++)
                st[r] = *(const float4*)(W + ((kb + 1) * 64 + kk_s[r]) * ldW + nbase + nn_s[r]);
        }
#pragma unroll 16
        for (int kk = 0; kk < 64; kk++) {
            float4 a = *(const float4*)(A_T + (kb * 64 + kk) * LDT + m0);
            float4 b = *(const float4*)(buf + kk * LDT + n0);
            c[0][0] += a.x * b.x; c[0][1] += a.x * b.y; c[0][2] += a.x * b.z; c[0][3] += a.x * b.w;
            c[1][0] += a.y * b.x; c[1][1] += a.y * b.y; c[1][2] += a.y * b.z; c[1][3] += a.y * b.w;
            c[2][0] += a.z * b.x; c[2][1] += a.z * b.y; c[2][2] += a.z * b.z; c[2][3] += a.z * b.w;
            c[3][0] += a.w * b.x; c[3][1] += a.w * b.y; c[3][2] += a.w * b.z; c[3][3] += a.w * b.w;
        }
        if (kb < 3) {
            __syncthreads();   // everyone done reading the buffer we are about to overwrite
            float* nbuf = Bst + ((kb + 1) & 1) * (64 * LDT);
#pragma unroll
            for (int r = 0; r < 4; r++)
                *(float4*)(nbuf + kk_s[r] * LDT + nn_s[r]) = st[r];
            __syncthreads();
        }
    }
    __syncthreads();  // safe for caller to reuse Bst / write A buffers
}

__global__ void __launch_bounds__(NT, 1)
dgsf_kernel(const float* __restrict__ score, const float* __restrict__ gate,
            const float* __restrict__ gumbel,
            const float* __restrict__ Wg,   const float* __restrict__ bg,
            const float* __restrict__ centers,
            const float* __restrict__ Wgm1, const float* __restrict__ bgm1,
            const float* __restrict__ Wgm2, const float* __restrict__ bgm2,
            const float* __restrict__ We1,  const float* __restrict__ be1,
            const float* __restrict__ We2,  const float* __restrict__ be2,
            const float* __restrict__ We3,  const float* __restrict__ be3,
            float* __restrict__ out, int N)
{
    extern __shared__ float sm[];
    float* A1   = sm + OFF_A1;
    float* A2   = sm + OFF_A2;
    float* Bst  = sm + OFF_B;
    float* z_s  = sm + OFF_Z;
    float* p_s  = sm + OFF_P;
    float* eo_s = sm + OFF_EO;

    const int t    = threadIdx.x;
    const int m0   = (t & 15) * 4;   // 4 rows per thread
    const int n0   = (t >> 4) * 4;   // 4 cols per thread
    const int row0 = blockIdx.x * BM;

    float c[4][4];

    // ================= gate path =================
    load_tile_T(A1, gate, row0, N, t);          // gate tile transposed -> A1

#pragma unroll
    for (int i = 0; i < 4; i++)
#pragma unroll
        for (int j = 0; j < 4; j++) c[i][j] = 0.f;
    gemm64(A1, Wg, 64, 0, Bst, c, m0, n0, t);   // gl = gate @ Wg   (L = 64 cols)
#pragma unroll
    for (int i = 0; i < 4; i++)
#pragma unroll
        for (int j = 0; j < 4; j++)
            A2[(n0 + j) * LDT + (m0 + i)] = c[i][j] + bg[n0 + j];   // gl_T -> A2
    __syncthreads();

    // squared distances to centers -> logits z_s[m][e] = -||gl - c_e||^2
    for (int p = t; p < 512; p += NT) {
        int m = p & 63, e = p >> 6;
        float acc = 0.f;
#pragma unroll 8
        for (int l = 0; l < 64; l++) {
            float diff = A2[l * LDT + m] - centers[e * 64 + l];
            acc += diff * diff;
        }
        z_s[m * 8 + e] = -acc;
    }
    __syncthreads();

    // gating MLP layer 1: a_T[h][m] = relu(z @ Wgm1 + bgm1) -> A1 (gate tile no longer needed)
    for (int p = t; p < 64 * 256; p += NT) {
        int m = p & 63, h = p >> 6;
        float acc = bgm1[h];
#pragma unroll
        for (int e = 0; e < 8; e++) acc += z_s[m * 8 + e] * Wgm1[e * 256 + h];
        A1[h * LDT + m] = fmaxf(acc, 0.f);
    }
    __syncthreads();

    // gating MLP layer 2 + gumbel -> z_s
    for (int p = t; p < 512; p += NT) {
        int m = p & 63, e = p >> 6;
        float acc = bgm2[e];
#pragma unroll 8
        for (int h = 0; h < 256; h++) acc += A1[h * LDT + m] * Wgm2[h * 8 + e];
        int row = row0 + m;
        if (row < N) acc += gumbel[(size_t)row * 8 + e];
        z_s[m * 8 + e] = acc;
    }
    __syncthreads();

    // softmax over E=8, fold be3 into eo accumulator init
    if (t < 64) {
        float mx = -1e30f;
#pragma unroll
        for (int e = 0; e < 8; e++) mx = fmaxf(mx, z_s[t * 8 + e]);
        float pe[8], s = 0.f;
#pragma unroll
        for (int e = 0; e < 8; e++) { pe[e] = __expf(z_s[t * 8 + e] - mx); s += pe[e]; }
        float inv = 1.f / s, eo = 0.f;
#pragma unroll
        for (int e = 0; e < 8; e++) {
            float pp = pe[e] * inv;
            p_s[t * 8 + e] = pp;
            eo += pp * be3[e];
        }
        eo_s[t] = eo;
    }
    __syncthreads();

    // ================= expert path =================
    load_tile_T(A1, score, row0, N, t);         // score tile transposed -> A1
    // (gemm64's internal barrier orders these writes before any compute reads)

    for (int e = 0; e < 8; e++) {
        const float* W1 = We1 + (size_t)e * 65536;
        const float* W2 = We2 + (size_t)e * 65536;
        const float* b1 = be1 + e * 256;
        const float* b2 = be2 + e * 256;
        const float* w3 = We3 + e * 256;

        // layer 1: h1 = relu(score @ W1 + b1) -> A2 (transposed)
        for (int nb = 0; nb < 4; nb++) {
#pragma unroll
            for (int i = 0; i < 4; i++)
#pragma unroll
                for (int j = 0; j < 4; j++) c[i][j] = 0.f;
            gemm64(A1, W1, 256, nb * 64, Bst, c, m0, n0, t);
#pragma unroll
            for (int i = 0; i < 4; i++)
#pragma unroll
                for (int j = 0; j < 4; j++) {
                    int n = nb * 64 + n0 + j;
                    A2[n * LDT + (m0 + i)] = fmaxf(c[i][j] + b1[n], 0.f);
                }
        }

        // layer 2 + layer 3 fused: eo += probs[e] * (relu(h1 @ W2 + b2) . We3[e])
        for (int nb = 0; nb < 4; nb++) {
#pragma unroll
            for (int i = 0; i < 4; i++)
#pragma unroll
                for (int j = 0; j < 4; j++) c[i][j] = 0.f;
            gemm64(A2, W2, 256, nb * 64, Bst, c, m0, n0, t);
#pragma unroll
            for (int i = 0; i < 4; i++) {
                float part = 0.f;
#pragma unroll
                for (int j = 0; j < 4; j++) {
                    int n = nb * 64 + n0 + j;
                    float v = fmaxf(c[i][j] + b2[n], 0.f);
                    part += v * w3[n];
                }
                atomicAdd(&eo_s[m0 + i], part * p_s[(m0 + i) * 8 + e]);
            }
        }
    }
    __syncthreads();

    if (t < 64) {
        int row = row0 + t;
        if (row < N) out[row] = 1.f / (1.f + __expf(-eo_s[t]));
    }
}

extern "C" void kernel_launch(void* const* d_in, const int* in_sizes, int n_in,
                              void* d_out, int out_size) {
    const float* score   = (const float*)d_in[0];
    const float* gate    = (const float*)d_in[1];
    const float* gumbel  = (const float*)d_in[2];
    const float* Wg      = (const float*)d_in[3];
    const float* bg      = (const float*)d_in[4];
    const float* centers = (const float*)d_in[5];
    const float* Wgm1    = (const float*)d_in[6];
    const float* bgm1    = (const float*)d_in[7];
    const float* Wgm2    = (const float*)d_in[8];
    const float* bgm2    = (const float*)d_in[9];
    const float* We1     = (const float*)d_in[10];
    const float* be1     = (const float*)d_in[11];
    const float* We2     = (const float*)d_in[12];
    const float* be2     = (const float*)d_in[13];
    const float* We3     = (const float*)d_in[14];
    const float* be3     = (const float*)d_in[15];
    float* out = (float*)d_out;

    int N = in_sizes[0] / 256;

    cudaFuncSetAttribute(dgsf_kernel, cudaFuncAttributeMaxDynamicSharedMemorySize, SMEM_BYTES);

    dim3 grid((N + BM - 1) / BM);
    dgsf_kernel<<<grid, NT, SMEM_BYTES>>>(score, gate, gumbel, Wg, bg, centers,
                                          Wgm1, bgm1, Wgm2, bgm2,
                                          We1, be1, We2, be2, We3, be3,
                                          out, N);
}

// round 5
// speedup vs baseline: 1.2576x; 1.2576x over previous
#include <cuda_runtime.h>
#include <math.h>

// Shapes fixed by reference: D=H=256, E=8, L=64
#define NT   256     // threads per block
#define BM   64      // rows per block
#define LDT  72      // padded row stride (floats) for transposed activation tiles

// shared memory layout (float offsets)
#define OFF_A1 0                          // [256][LDT]  gate/score tile transposed
#define OFF_A2 (256 * LDT)                // [256][LDT]  gl_T / h1_T
#define OFF_B  (2 * 256 * LDT)            // 16384 floats: 2 x [32][256] weight chunks (or Wg stage)
#define OFF_Z  (OFF_B + 16384)            // [64][8] logits
#define OFF_P  (OFF_Z + 512)              // [64][8] probs
#define OFF_EO (OFF_P + 512)              // [64]    weighted expert-output accumulator
#define SMEM_FLOATS (OFF_EO + 64)
#define SMEM_BYTES  (SMEM_FLOATS * 4)

// Load [64 x 256] fp32 tile, store transposed dst[k][m]. Thread t owns row m=t&63,
// k-range (t>>6)*64..+63. STS: lanes = consecutive m at same k -> conflict-free.
__device__ __forceinline__ void load_tile_T(float* dst, const float* __restrict__ src,
                                            int row0, int N, int t) {
    int m   = t & 63;
    int kg  = (t >> 6) * 64;
    int row = row0 + m;
    const float* s = src + (size_t)row * 256 + kg;
#pragma unroll
    for (int r = 0; r < 16; r++) {
        float4 v = make_float4(0.f, 0.f, 0.f, 0.f);
        if (row < N) v = *(const float4*)(s + r * 4);
        int k = kg + r * 4;
        dst[(k + 0) * LDT + m] = v.x;
        dst[(k + 1) * LDT + m] = v.y;
        dst[(k + 2) * LDT + m] = v.z;
        dst[(k + 3) * LDT + m] = v.w;
    }
}

// C[64 x 256] += A_T(256xK transposed in smem) @ W[256][256] (row-major, n contiguous).
// 8x8 per thread. K streamed in 8 chunks of 32 rows, double-buffered via registers.
__device__ __forceinline__ void gemm256(const float* __restrict__ A_T,
                                        const float* __restrict__ W,
                                        float* Bst, float c[8][8], int m0, int n0, int t) {
    float4 st[8];
    int kk_s[8], nn_s[8];
#pragma unroll
    for (int r = 0; r < 8; r++) {
        int p   = t + NT * r;       // 0..2047 float4 slots of a [32k x 256n] chunk
        kk_s[r] = p >> 6;           // 0..31
        nn_s[r] = (p & 63) << 2;    // 0..252
    }
    // prologue: stage chunk 0
#pragma unroll
    for (int r = 0; r < 8; r++)
        st[r] = *(const float4*)(W + kk_s[r] * 256 + nn_s[r]);
#pragma unroll
    for (int r = 0; r < 8; r++)
        *(float4*)(Bst + kk_s[r] * 256 + nn_s[r]) = st[r];
    __syncthreads();

    for (int cb = 0; cb < 8; cb++) {
        const float* buf = Bst + (cb & 1) * (32 * 256) + n0;
        const float* ap  = A_T + (cb * 32) * LDT + m0;
        if (cb < 7) {  // prefetch next chunk into registers (overlaps with FMAs)
#pragma unroll
            for (int r = 0; r < 8; r++)
                st[r] = *(const float4*)(W + ((cb + 1) * 32 + kk_s[r]) * 256 + nn_s[r]);
        }
#pragma unroll 8
        for (int kk = 0; kk < 32; kk++) {
            float4 a0 = *(const float4*)(ap + kk * LDT);
            float4 a1 = *(const float4*)(ap + kk * LDT + 4);
            float4 b0 = *(const float4*)(buf + kk * 256);
            float4 b1 = *(const float4*)(buf + kk * 256 + 4);
            float a[8] = {a0.x, a0.y, a0.z, a0.w, a1.x, a1.y, a1.z, a1.w};
            float b[8] = {b0.x, b0.y, b0.z, b0.w, b1.x, b1.y, b1.z, b1.w};
#pragma unroll
            for (int i = 0; i < 8; i++)
#pragma unroll
                for (int j = 0; j < 8; j++)
                    c[i][j] += a[i] * b[j];
        }
        if (cb < 7) {
            __syncthreads();   // everyone done reading buffer about to be overwritten
            float* nbuf = Bst + ((cb + 1) & 1) * (32 * 256);
#pragma unroll
            for (int r = 0; r < 8; r++)
                *(float4*)(nbuf + kk_s[r] * 256 + nn_s[r]) = st[r];
            __syncthreads();
        }
    }
    __syncthreads();  // caller may reuse Bst / A buffers
}

__global__ void __launch_bounds__(NT, 1)
dgsf_kernel(const float* __restrict__ score, const float* __restrict__ gate,
            const float* __restrict__ gumbel,
            const float* __restrict__ Wg,   const float* __restrict__ bg,
            const float* __restrict__ centers,
            const float* __restrict__ Wgm1, const float* __restrict__ bgm1,
            const float* __restrict__ Wgm2, const float* __restrict__ bgm2,
            const float* __restrict__ We1,  const float* __restrict__ be1,
            const float* __restrict__ We2,  const float* __restrict__ be2,
            const float* __restrict__ We3,  const float* __restrict__ be3,
            float* __restrict__ out, int N)
{
    extern __shared__ float sm[];
    float* A1   = sm + OFF_A1;
    float* A2   = sm + OFF_A2;
    float* Bst  = sm + OFF_B;
    float* z_s  = sm + OFF_Z;
    float* p_s  = sm + OFF_P;
    float* eo_s = sm + OFF_EO;

    const int t    = threadIdx.x;
    const int row0 = blockIdx.x * BM;
    const int m0   = (t & 7) * 8;    // 8 rows per thread
    const int n0   = (t >> 3) * 8;   // 8 cols per thread

    // ================= gate path =================
    load_tile_T(A1, gate, row0, N, t);          // gate tile transposed -> A1

    // stage Wg [256][64] into Bst (fits: 16384 floats)
#pragma unroll
    for (int r = 0; r < 16; r++) {
        int p  = t + NT * r;          // 0..4095 float4 slots
        int k  = p >> 4;              // 0..255
        int n4 = (p & 15) << 2;       // 0..60
        *(float4*)(Bst + k * 64 + n4) = *(const float4*)(Wg + k * 64 + n4);
    }
    __syncthreads();   // orders A1 stores + Wg stage

    // gl_T = (gate @ Wg + bg)^T -> A2. Thread: row m=t&63, 16 L-cols.
    {
        int m = t & 63, lg = (t >> 6) * 16;
        float acc[16];
#pragma unroll
        for (int j = 0; j < 16; j++) acc[j] = bg[lg + j];
#pragma unroll 4
        for (int k = 0; k < 256; k++) {
            float a = A1[k * LDT + m];
            const float4* wp = (const float4*)(Bst + k * 64 + lg);
#pragma unroll
            for (int q = 0; q < 4; q++) {
                float4 w = wp[q];
                acc[q * 4 + 0] += a * w.x;
                acc[q * 4 + 1] += a * w.y;
                acc[q * 4 + 2] += a * w.z;
                acc[q * 4 + 3] += a * w.w;
            }
        }
#pragma unroll
        for (int j = 0; j < 16; j++)
            A2[(lg + j) * LDT + m] = acc[j];
    }
    __syncthreads();

    // logits z_s[m][e] = -||gl - c_e||^2
    for (int p = t; p < 512; p += NT) {
        int m = p & 63, e = p >> 6;
        float acc = 0.f;
#pragma unroll 8
        for (int l = 0; l < 64; l++) {
            float diff = A2[l * LDT + m] - centers[e * 64 + l];
            acc += diff * diff;
        }
        z_s[m * 8 + e] = -acc;
    }
    __syncthreads();

    // gating MLP layer 1 -> A1 (gate tile no longer needed)
    for (int p = t; p < 64 * 256; p += NT) {
        int m = p & 63, h = p >> 6;
        float acc = bgm1[h];
#pragma unroll
        for (int e = 0; e < 8; e++) acc += z_s[m * 8 + e] * Wgm1[e * 256 + h];
        A1[h * LDT + m] = fmaxf(acc, 0.f);
    }
    __syncthreads();

    // gating MLP layer 2 + gumbel -> z_s
    for (int p = t; p < 512; p += NT) {
        int m = p & 63, e = p >> 6;
        float acc = bgm2[e];
#pragma unroll 8
        for (int h = 0; h < 256; h++) acc += A1[h * LDT + m] * Wgm2[h * 8 + e];
        int row = row0 + m;
        if (row < N) acc += gumbel[(size_t)row * 8 + e];
        z_s[m * 8 + e] = acc;
    }
    __syncthreads();

    // softmax over E=8, fold be3 into eo init
    if (t < 64) {
        float mx = -1e30f;
#pragma unroll
        for (int e = 0; e < 8; e++) mx = fmaxf(mx, z_s[t * 8 + e]);
        float pe[8], s = 0.f;
#pragma unroll
        for (int e = 0; e < 8; e++) { pe[e] = __expf(z_s[t * 8 + e] - mx); s += pe[e]; }
        float inv = 1.f / s, eo = 0.f;
#pragma unroll
        for (int e = 0; e < 8; e++) {
            float pp = pe[e] * inv;
            p_s[t * 8 + e] = pp;
            eo += pp * be3[e];
        }
        eo_s[t] = eo;
    }
    __syncthreads();

    // ================= expert path =================
    load_tile_T(A1, score, row0, N, t);   // score tile transposed -> A1
    // (gemm256's first internal barrier orders these stores before compute reads)

    float c[8][8];
    for (int e = 0; e < 8; e++) {
        const float* W1 = We1 + (size_t)e * 65536;
        const float* W2 = We2 + (size_t)e * 65536;
        const float* b1 = be1 + e * 256;
        const float* b2 = be2 + e * 256;
        const float* w3 = We3 + e * 256;

        // layer 1: h1 = relu(score @ W1 + b1) -> A2 transposed [n][m]
#pragma unroll
        for (int i = 0; i < 8; i++)
#pragma unroll
            for (int j = 0; j < 8; j++) c[i][j] = 0.f;
        gemm256(A1, W1, Bst, c, m0, n0, t);
#pragma unroll
        for (int j = 0; j < 8; j++) {
            int n = n0 + j;
            float bb = b1[n];
            float4 v0 = make_float4(fmaxf(c[0][j] + bb, 0.f), fmaxf(c[1][j] + bb, 0.f),
                                    fmaxf(c[2][j] + bb, 0.f), fmaxf(c[3][j] + bb, 0.f));
            float4 v1 = make_float4(fmaxf(c[4][j] + bb, 0.f), fmaxf(c[5][j] + bb, 0.f),
                                    fmaxf(c[6][j] + bb, 0.f), fmaxf(c[7][j] + bb, 0.f));
            *(float4*)(A2 + n * LDT + m0)     = v0;
            *(float4*)(A2 + n * LDT + m0 + 4) = v1;
        }
        // (layer-2 gemm's first internal barrier orders A2 stores before reads)

        // layer 2 + layer 3 fused
#pragma unroll
        for (int i = 0; i < 8; i++)
#pragma unroll
            for (int j = 0; j < 8; j++) c[i][j] = 0.f;
        gemm256(A2, W2, Bst, c, m0, n0, t);

        float part[8];
#pragma unroll
        for (int i = 0; i < 8; i++) {
            float s = 0.f;
#pragma unroll
            for (int j = 0; j < 8; j++) {
                int n = n0 + j;
                float v = fmaxf(c[i][j] + b2[n], 0.f);
                s += v * w3[n];
            }
            part[i] = s;
        }
        // reduce across the 4 lanes sharing the same m-group (lane ^ 8, ^ 16)
#pragma unroll
        for (int i = 0; i < 8; i++) {
            part[i] += __shfl_xor_sync(0xffffffffu, part[i], 8);
            part[i] += __shfl_xor_sync(0xffffffffu, part[i], 16);
        }
        if (((t >> 3) & 3) == 0) {   // lanes 0..7 of each warp
#pragma unroll
            for (int i = 0; i < 8; i++) {
                int m = m0 + i;
                atomicAdd(&eo_s[m], part[i] * p_s[m * 8 + e]);
            }
        }
    }
    __syncthreads();

    if (t < 64) {
        int row = row0 + t;
        if (row < N) out[row] = 1.f / (1.f + __expf(-eo_s[t]));
    }
}

extern "C" void kernel_launch(void* const* d_in, const int* in_sizes, int n_in,
                              void* d_out, int out_size) {
    const float* score   = (const float*)d_in[0];
    const float* gate    = (const float*)d_in[1];
    const float* gumbel  = (const float*)d_in[2];
    const float* Wg      = (const float*)d_in[3];
    const float* bg      = (const float*)d_in[4];
    const float* centers = (const float*)d_in[5];
    const float* Wgm1    = (const float*)d_in[6];
    const float* bgm1    = (const float*)d_in[7];
    const float* Wgm2    = (const float*)d_in[8];
    const float* bgm2    = (const float*)d_in[9];
    const float* We1     = (const float*)d_in[10];
    const float* be1     = (const float*)d_in[11];
    const float* We2     = (const float*)d_in[12];
    const float* be2     = (const float*)d_in[13];
    const float* We3     = (const float*)d_in[14];
    const float* be3     = (const float*)d_in[15];
    float* out = (float*)d_out;

    int N = in_sizes[0] / 256;

    cudaFuncSetAttribute(dgsf_kernel, cudaFuncAttributeMaxDynamicSharedMemorySize, SMEM_BYTES);

    dim3 grid((N + BM - 1) / BM);
    dgsf_kernel<<<grid, NT, SMEM_BYTES>>>(score, gate, gumbel, Wg, bg, centers,
                                          Wgm1, bgm1, Wgm2, bgm2,
                                          We1, be1, We2, be2, We3, be3,
                                          out, N);
}

// round 6
// speedup vs baseline: 1.2590x; 1.0011x over previous
#include <cuda_runtime.h>
#include <math.h>

// Shapes fixed by reference: D=H=256, E=8, L=64
#define NT   256     // threads per block
#define BM   64      // rows per block
#define LDT  72      // padded row stride (floats) for transposed activation tiles

// shared memory layout (float offsets)
#define OFF_A1 0                          // [256][LDT]  gate/score tile transposed
#define OFF_A2 (256 * LDT)                // [256][LDT]  gl_T / h1_T
#define OFF_B  (2 * 256 * LDT)            // 16384 floats: 2 x [32][256] weight chunks (or Wg stage)
#define OFF_Z  (OFF_B + 16384)            // [64][8] logits
#define OFF_P  (OFF_Z + 512)              // [64][8] probs
#define OFF_EO (OFF_P + 512)              // [64]    weighted expert-output accumulator
#define SMEM_FLOATS (OFF_EO + 64)
#define SMEM_BYTES  (SMEM_FLOATS * 4)

// Load [64 x 256] fp32 tile, store transposed dst[k][m]. Thread t owns row m=t&63,
// k-range (t>>6)*64..+63. STS: lanes = consecutive m at same k -> conflict-free.
__device__ __forceinline__ void load_tile_T(float* dst, const float* __restrict__ src,
                                            int row0, int N, int t) {
    int m   = t & 63;
    int kg  = (t >> 6) * 64;
    int row = row0 + m;
    const float* s = src + (size_t)row * 256 + kg;
#pragma unroll
    for (int r = 0; r < 16; r++) {
        float4 v = make_float4(0.f, 0.f, 0.f, 0.f);
        if (row < N) v = *(const float4*)(s + r * 4);
        int k = kg + r * 4;
        dst[(k + 0) * LDT + m] = v.x;
        dst[(k + 1) * LDT + m] = v.y;
        dst[(k + 2) * LDT + m] = v.z;
        dst[(k + 3) * LDT + m] = v.w;
    }
}

// C[64 x 256] += A_T(256xK transposed in smem) @ W[256][256] (row-major, n contiguous).
// 8x8 per thread. K streamed in 8 chunks of 32 rows, double-buffered via registers.
__device__ __forceinline__ void gemm256(const float* __restrict__ A_T,
                                        const float* __restrict__ W,
                                        float* Bst, float c[8][8], int m0, int n0, int t) {
    float4 st[8];
    int kk_s[8], nn_s[8];
#pragma unroll
    for (int r = 0; r < 8; r++) {
        int p   = t + NT * r;       // 0..2047 float4 slots of a [32k x 256n] chunk
        kk_s[r] = p >> 6;           // 0..31
        nn_s[r] = (p & 63) << 2;    // 0..252
    }
    // prologue: stage chunk 0
#pragma unroll
    for (int r = 0; r < 8; r++)
        st[r] = *(const float4*)(W + kk_s[r] * 256 + nn_s[r]);
#pragma unroll
    for (int r = 0; r < 8; r++)
        *(float4*)(Bst + kk_s[r] * 256 + nn_s[r]) = st[r];
    __syncthreads();

    for (int cb = 0; cb < 8; cb++) {
        const float* buf = Bst + (cb & 1) * (32 * 256) + n0;
        const float* ap  = A_T + (cb * 32) * LDT + m0;
        if (cb < 7) {  // prefetch next chunk into registers (overlaps with FMAs)
#pragma unroll
            for (int r = 0; r < 8; r++)
                st[r] = *(const float4*)(W + ((cb + 1) * 32 + kk_s[r]) * 256 + nn_s[r]);
        }
#pragma unroll 8
        for (int kk = 0; kk < 32; kk++) {
            float4 a0 = *(const float4*)(ap + kk * LDT);
            float4 a1 = *(const float4*)(ap + kk * LDT + 4);
            float4 b0 = *(const float4*)(buf + kk * 256);
            float4 b1 = *(const float4*)(buf + kk * 256 + 4);
            float a[8] = {a0.x, a0.y, a0.z, a0.w, a1.x, a1.y, a1.z, a1.w};
            float b[8] = {b0.x, b0.y, b0.z, b0.w, b1.x, b1.y, b1.z, b1.w};
#pragma unroll
            for (int i = 0; i < 8; i++)
#pragma unroll
                for (int j = 0; j < 8; j++)
                    c[i][j] += a[i] * b[j];
        }
        if (cb < 7) {
            __syncthreads();   // everyone done reading buffer about to be overwritten
            float* nbuf = Bst + ((cb + 1) & 1) * (32 * 256);
#pragma unroll
            for (int r = 0; r < 8; r++)
                *(float4*)(nbuf + kk_s[r] * 256 + nn_s[r]) = st[r];
            __syncthreads();
        }
    }
    __syncthreads();  // caller may reuse Bst / A buffers
}

__global__ void __launch_bounds__(NT, 1)
dgsf_kernel(const float* __restrict__ score, const float* __restrict__ gate,
            const float* __restrict__ gumbel,
            const float* __restrict__ Wg,   const float* __restrict__ bg,
            const float* __restrict__ centers,
            const float* __restrict__ Wgm1, const float* __restrict__ bgm1,
            const float* __restrict__ Wgm2, const float* __restrict__ bgm2,
            const float* __restrict__ We1,  const float* __restrict__ be1,
            const float* __restrict__ We2,  const float* __restrict__ be2,
            const float* __restrict__ We3,  const float* __restrict__ be3,
            float* __restrict__ out, int N)
{
    extern __shared__ float sm[];
    float* A1   = sm + OFF_A1;
    float* A2   = sm + OFF_A2;
    float* Bst  = sm + OFF_B;
    float* z_s  = sm + OFF_Z;
    float* p_s  = sm + OFF_P;
    float* eo_s = sm + OFF_EO;

    const int t    = threadIdx.x;
    const int row0 = blockIdx.x * BM;
    const int m0   = (t & 7) * 8;    // 8 rows per thread
    const int n0   = (t >> 3) * 8;   // 8 cols per thread

    // ================= gate path =================
    load_tile_T(A1, gate, row0, N, t);          // gate tile transposed -> A1

    // stage Wg [256][64] into Bst (fits: 16384 floats)
#pragma unroll
    for (int r = 0; r < 16; r++) {
        int p  = t + NT * r;          // 0..4095 float4 slots
        int k  = p >> 4;              // 0..255
        int n4 = (p & 15) << 2;       // 0..60
        *(float4*)(Bst + k * 64 + n4) = *(const float4*)(Wg + k * 64 + n4);
    }
    __syncthreads();   // orders A1 stores + Wg stage

    // gl_T = (gate @ Wg + bg)^T -> A2. Thread: row m=t&63, 16 L-cols.
    {
        int m = t & 63, lg = (t >> 6) * 16;
        float acc[16];
#pragma unroll
        for (int j = 0; j < 16; j++) acc[j] = bg[lg + j];
#pragma unroll 4
        for (int k = 0; k < 256; k++) {
            float a = A1[k * LDT + m];
            const float4* wp = (const float4*)(Bst + k * 64 + lg);
#pragma unroll
            for (int q = 0; q < 4; q++) {
                float4 w = wp[q];
                acc[q * 4 + 0] += a * w.x;
                acc[q * 4 + 1] += a * w.y;
                acc[q * 4 + 2] += a * w.z;
                acc[q * 4 + 3] += a * w.w;
            }
        }
#pragma unroll
        for (int j = 0; j < 16; j++)
            A2[(lg + j) * LDT + m] = acc[j];
    }
    __syncthreads();

    // logits z_s[m][e] = -||gl - c_e||^2
    for (int p = t; p < 512; p += NT) {
        int m = p & 63, e = p >> 6;
        float acc = 0.f;
#pragma unroll 8
        for (int l = 0; l < 64; l++) {
            float diff = A2[l * LDT + m] - centers[e * 64 + l];
            acc += diff * diff;
        }
        z_s[m * 8 + e] = -acc;
    }
    __syncthreads();

    // gating MLP layer 1 -> A1 (gate tile no longer needed)
    for (int p = t; p < 64 * 256; p += NT) {
        int m = p & 63, h = p >> 6;
        float acc = bgm1[h];
#pragma unroll
        for (int e = 0; e < 8; e++) acc += z_s[m * 8 + e] * Wgm1[e * 256 + h];
        A1[h * LDT + m] = fmaxf(acc, 0.f);
    }
    __syncthreads();

    // gating MLP layer 2 + gumbel -> z_s
    for (int p = t; p < 512; p += NT) {
        int m = p & 63, e = p >> 6;
        float acc = bgm2[e];
#pragma unroll 8
        for (int h = 0; h < 256; h++) acc += A1[h * LDT + m] * Wgm2[h * 8 + e];
        int row = row0 + m;
        if (row < N) acc += gumbel[(size_t)row * 8 + e];
        z_s[m * 8 + e] = acc;
    }
    __syncthreads();

    // softmax over E=8, fold be3 into eo init
    if (t < 64) {
        float mx = -1e30f;
#pragma unroll
        for (int e = 0; e < 8; e++) mx = fmaxf(mx, z_s[t * 8 + e]);
        float pe[8], s = 0.f;
#pragma unroll
        for (int e = 0; e < 8; e++) { pe[e] = __expf(z_s[t * 8 + e] - mx); s += pe[e]; }
        float inv = 1.f / s, eo = 0.f;
#pragma unroll
        for (int e = 0; e < 8; e++) {
            float pp = pe[e] * inv;
            p_s[t * 8 + e] = pp;
            eo += pp * be3[e];
        }
        eo_s[t] = eo;
    }
    __syncthreads();

    // ================= expert path =================
    load_tile_T(A1, score, row0, N, t);   // score tile transposed -> A1
    // (gemm256's first internal barrier orders these stores before compute reads)

    float c[8][8];
    for (int e = 0; e < 8; e++) {
        const float* W1 = We1 + (size_t)e * 65536;
        const float* W2 = We2 + (size_t)e * 65536;
        const float* b1 = be1 + e * 256;
        const float* b2 = be2 + e * 256;
        const float* w3 = We3 + e * 256;

        // layer 1: h1 = relu(score @ W1 + b1) -> A2 transposed [n][m]
#pragma unroll
        for (int i = 0; i < 8; i++)
#pragma unroll
            for (int j = 0; j < 8; j++) c[i][j] = 0.f;
        gemm256(A1, W1, Bst, c, m0, n0, t);
#pragma unroll
        for (int j = 0; j < 8; j++) {
            int n = n0 + j;
            float bb = b1[n];
            float4 v0 = make_float4(fmaxf(c[0][j] + bb, 0.f), fmaxf(c[1][j] + bb, 0.f),
                                    fmaxf(c[2][j] + bb, 0.f), fmaxf(c[3][j] + bb, 0.f));
            float4 v1 = make_float4(fmaxf(c[4][j] + bb, 0.f), fmaxf(c[5][j] + bb, 0.f),
                                    fmaxf(c[6][j] + bb, 0.f), fmaxf(c[7][j] + bb, 0.f));
            *(float4*)(A2 + n * LDT + m0)     = v0;
            *(float4*)(A2 + n * LDT + m0 + 4) = v1;
        }
        // (layer-2 gemm's first internal barrier orders A2 stores before reads)

        // layer 2 + layer 3 fused
#pragma unroll
        for (int i = 0; i < 8; i++)
#pragma unroll
            for (int j = 0; j < 8; j++) c[i][j] = 0.f;
        gemm256(A2, W2, Bst, c, m0, n0, t);

        float part[8];
#pragma unroll
        for (int i = 0; i < 8; i++) {
            float s = 0.f;
#pragma unroll
            for (int j = 0; j < 8; j++) {
                int n = n0 + j;
                float v = fmaxf(c[i][j] + b2[n], 0.f);
                s += v * w3[n];
            }
            part[i] = s;
        }
        // reduce across the 4 lanes sharing the same m-group (lane ^ 8, ^ 16)
#pragma unroll
        for (int i = 0; i < 8; i++) {
            part[i] += __shfl_xor_sync(0xffffffffu, part[i], 8);
            part[i] += __shfl_xor_sync(0xffffffffu, part[i], 16);
        }
        if (((t >> 3) & 3) == 0) {   // lanes 0..7 of each warp
#pragma unroll
            for (int i = 0; i < 8; i++) {
                int m = m0 + i;
                atomicAdd(&eo_s[m], part[i] * p_s[m * 8 + e]);
            }
        }
    }
    __syncthreads();

    if (t < 64) {
        int row = row0 + t;
        if (row < N) out[row] = 1.f / (1.f + __expf(-eo_s[t]));
    }
}

extern "C" void kernel_launch(void* const* d_in, const int* in_sizes, int n_in,
                              void* d_out, int out_size) {
    const float* score   = (const float*)d_in[0];
    const float* gate    = (const float*)d_in[1];
    const float* gumbel  = (const float*)d_in[2];
    const float* Wg      = (const float*)d_in[3];
    const float* bg      = (const float*)d_in[4];
    const float* centers = (const float*)d_in[5];
    const float* Wgm1    = (const float*)d_in[6];
    const float* bgm1    = (const float*)d_in[7];
    const float* Wgm2    = (const float*)d_in[8];
    const float* bgm2    = (const float*)d_in[9];
    const float* We1     = (const float*)d_in[10];
    const float* be1     = (const float*)d_in[11];
    const float* We2     = (const float*)d_in[12];
    const float* be2     = (const float*)d_in[13];
    const float* We3     = (const float*)d_in[14];
    const float* be3     = (const float*)d_in[15];
    float* out = (float*)d_out;

    int N = in_sizes[0] / 256;

    cudaFuncSetAttribute(dgsf_kernel, cudaFuncAttributeMaxDynamicSharedMemorySize, SMEM_BYTES);

    dim3 grid((N + BM - 1) / BM);
    dgsf_kernel<<<grid, NT, SMEM_BYTES>>>(score, gate, gumbel, Wg, bg, centers,
                                          Wgm1, bgm1, Wgm2, bgm2,
                                          We1, be1, We2, be2, We3, be3,
                                          out, N);
}